// round 1
// baseline (speedup 1.0000x reference)
#include <cuda_runtime.h>
#include <cuda_bf16.h>
#include <cstdint>
#include <cstdio>

// Problem constants (fixed by reference)
#define NQc 900
#define Bc  8
#define Dc  256
#define Hc  8
#define DHc 32
#define NLc 4
#define NPc 4
#define DFFc 1024
#define Sc  19947
#define Tc  (NQc*Bc)        // 7200 tokens

// ---------------- scratch (device globals; no allocation) ----------------
__device__ float g_qin [Tc*Dc];
__device__ float g_q   [Tc*Dc];
__device__ float g_k   [Tc*Dc];
__device__ float g_v   [Tc*Dc];
__device__ float g_ao  [Tc*Dc];
__device__ float g_t1  [Tc*Dc];
__device__ float g_tgt2[Tc*Dc];
__device__ float g_qca [Tc*Dc];
__device__ float g_off [Tc*Dc];
__device__ float g_aw  [Tc*128];
__device__ float g_ca  [Tc*Dc];
__device__ float g_tgt3[Tc*Dc];
__device__ float g_ffn [Tc*DFFc];
__device__ float g_value[(size_t)Sc*Bc*Dc];

// ---------------- elementwise add ----------------
__global__ void add_k(const float* __restrict__ a, const float* __restrict__ b,
                      float* __restrict__ c, int n) {
    int i = blockIdx.x*256 + threadIdx.x;
    if (i < n) c[i] = a[i] + b[i];
}

// ---------------- tiled SGEMM:  C[M,N] = A[M,K] @ W[N,K]^T + bias  ----------------
template<int RELU>
__global__ void sgemm(const float* __restrict__ A, const float* __restrict__ W,
                      const float* __restrict__ bias, float* __restrict__ C,
                      int M, int N, int K) {
    __shared__ float As[16][68];
    __shared__ float Ws[16][68];
    int tid = threadIdx.x;
    int tx = tid & 15, ty = tid >> 4;
    int row0 = blockIdx.y * 64, col0 = blockIdx.x * 64;
    float acc[4][4] = {};
    for (int k0 = 0; k0 < K; k0 += 16) {
        #pragma unroll
        for (int i = 0; i < 4; i++) {
            int idx = tid + i*256;
            int r = idx >> 4, kk = idx & 15;
            int gr = row0 + r;
            int gc = col0 + r;
            As[kk][r] = (gr < M) ? A[(size_t)gr*K + k0 + kk] : 0.f;
            Ws[kk][r] = (gc < N) ? W[(size_t)gc*K + k0 + kk] : 0.f;
        }
        __syncthreads();
        #pragma unroll
        for (int kk = 0; kk < 16; kk++) {
            float a[4], w[4];
            #pragma unroll
            for (int i = 0; i < 4; i++) { a[i] = As[kk][ty*4+i]; w[i] = Ws[kk][tx*4+i]; }
            #pragma unroll
            for (int i = 0; i < 4; i++)
                #pragma unroll
                for (int j = 0; j < 4; j++)
                    acc[i][j] += a[i]*w[j];
        }
        __syncthreads();
    }
    #pragma unroll
    for (int i = 0; i < 4; i++) {
        int gr = row0 + ty*4 + i;
        if (gr >= M) continue;
        #pragma unroll
        for (int j = 0; j < 4; j++) {
            int gc = col0 + tx*4 + j;
            if (gc < N) {
                float v = acc[i][j] + bias[gc];
                if (RELU) v = fmaxf(v, 0.f);
                C[(size_t)gr*N + gc] = v;
            }
        }
    }
}

// ---------------- fused self-attention (4 query rows / block) ----------------
__global__ void attn_kernel(const float* __restrict__ Q, const float* __restrict__ K,
                            const float* __restrict__ V, float* __restrict__ O) {
    __shared__ float sc[4][NQc];
    __shared__ float qs[4][32];
    __shared__ float rsum[4];
    __shared__ float part[4][4][32];
    int b = blockIdx.z, h = blockIdx.y, l0 = blockIdx.x * 4;
    int tid = threadIdx.x, w = tid >> 5, lane = tid & 31;

    {   // load 4 scaled q rows
        int r = tid >> 5, d = tid & 31;
        qs[r][d] = Q[((size_t)(l0+r)*Bc + b)*Dc + h*DHc + d] * 0.17677669529663689f;
    }
    __syncthreads();

    // scores: warp w handles m = w, w+4, ...
    for (int m = w; m < NQc; m += 4) {
        float kv = K[((size_t)m*Bc + b)*Dc + h*DHc + lane];
        float d0 = qs[0][lane]*kv;
        float d1 = qs[1][lane]*kv;
        float d2 = qs[2][lane]*kv;
        float d3 = qs[3][lane]*kv;
        #pragma unroll
        for (int o = 16; o; o >>= 1) {
            d0 += __shfl_xor_sync(0xffffffffu, d0, o);
            d1 += __shfl_xor_sync(0xffffffffu, d1, o);
            d2 += __shfl_xor_sync(0xffffffffu, d2, o);
            d3 += __shfl_xor_sync(0xffffffffu, d3, o);
        }
        if (lane == 0) { sc[0][m]=d0; sc[1][m]=d1; sc[2][m]=d2; sc[3][m]=d3; }
    }
    __syncthreads();

    // softmax: warp w owns row w
    {
        float mx = -1e30f;
        for (int m = lane; m < NQc; m += 32) mx = fmaxf(mx, sc[w][m]);
        #pragma unroll
        for (int o = 16; o; o >>= 1) mx = fmaxf(mx, __shfl_xor_sync(0xffffffffu, mx, o));
        float s = 0.f;
        for (int m = lane; m < NQc; m += 32) { float e = __expf(sc[w][m]-mx); sc[w][m] = e; s += e; }
        #pragma unroll
        for (int o = 16; o; o >>= 1) s += __shfl_xor_sync(0xffffffffu, s, o);
        if (lane == 0) rsum[w] = 1.f/s;
    }
    __syncthreads();

    // output: each warp takes m-stride, accumulates all 4 rows
    float a0=0.f, a1=0.f, a2=0.f, a3=0.f;
    for (int m = w; m < NQc; m += 4) {
        float vv = V[((size_t)m*Bc + b)*Dc + h*DHc + lane];
        a0 += sc[0][m]*vv; a1 += sc[1][m]*vv; a2 += sc[2][m]*vv; a3 += sc[3][m]*vv;
    }
    part[w][0][lane]=a0; part[w][1][lane]=a1; part[w][2][lane]=a2; part[w][3][lane]=a3;
    __syncthreads();
    {
        int r = tid >> 5, d = tid & 31;
        float s = part[0][r][d] + part[1][r][d] + part[2][r][d] + part[3][r][d];
        O[((size_t)(l0+r)*Bc + b)*Dc + h*DHc + d] = s * rsum[r];
    }
}

// ---------------- residual + LayerNorm ----------------
__global__ void residual_ln(const float* __restrict__ res, const float* __restrict__ x,
                            const float* __restrict__ g, const float* __restrict__ be,
                            float* __restrict__ out) {
    int t = blockIdx.x, i = threadIdx.x;
    float v = res[(size_t)t*Dc + i] + x[(size_t)t*Dc + i];
    __shared__ float red[8];
    __shared__ float mean_s, rstd_s;
    float s = v;
    #pragma unroll
    for (int o = 16; o; o >>= 1) s += __shfl_xor_sync(0xffffffffu, s, o);
    if ((i & 31) == 0) red[i >> 5] = s;
    __syncthreads();
    if (i < 32) {
        float t2 = (i < 8) ? red[i] : 0.f;
        #pragma unroll
        for (int o = 4; o; o >>= 1) t2 += __shfl_xor_sync(0xffffffffu, t2, o);
        if (i == 0) mean_s = t2 * (1.f/Dc);
    }
    __syncthreads();
    float m = mean_s;
    float d = v - m;
    float sq = d*d;
    #pragma unroll
    for (int o = 16; o; o >>= 1) sq += __shfl_xor_sync(0xffffffffu, sq, o);
    if ((i & 31) == 0) red[i >> 5] = sq;
    __syncthreads();
    if (i < 32) {
        float t2 = (i < 8) ? red[i] : 0.f;
        #pragma unroll
        for (int o = 4; o; o >>= 1) t2 += __shfl_xor_sync(0xffffffffu, t2, o);
        if (i == 0) rstd_s = rsqrtf(t2 * (1.f/Dc) + 1e-5f);
    }
    __syncthreads();
    out[(size_t)t*Dc + i] = d * rstd_s * g[i] + be[i];
}

// ---------------- MS-deformable attention sampling ----------------
__global__ void deform_kernel(const float* __restrict__ off, const float* __restrict__ aw,
                              const float* __restrict__ ref, const float* __restrict__ value,
                              float* __restrict__ out) {
    int q = blockIdx.x, b = blockIdx.y;
    int t = q*Bc + b;
    int tid = threadIdx.x, h = tid >> 5, lane = tid & 31;

    // softmax over the 16 (level, point) weights of this head
    float a = (lane < 16) ? aw[(size_t)t*128 + h*16 + lane] : -1e30f;
    float mx = a;
    #pragma unroll
    for (int o = 16; o; o >>= 1) mx = fmaxf(mx, __shfl_xor_sync(0xffffffffu, mx, o));
    float e = (lane < 16) ? __expf(a - mx) : 0.f;
    float s = e;
    #pragma unroll
    for (int o = 16; o; o >>= 1) s += __shfl_xor_sync(0xffffffffu, s, o);
    float wgt = e / s;

    const float* rp = ref + (size_t)t*(NLc*4);
    const float* op = off + (size_t)t*Dc + h*32;
    const int HH[4] = {100,50,25,13};
    const int WW[4] = {150,75,38,19};
    const int ST[4] = {0,15000,18750,19700};
    float acc = 0.f;
    #pragma unroll
    for (int l = 0; l < NLc; l++) {
        float r0 = rp[l*4+0], r1 = rp[l*4+1], r2 = rp[l*4+2], r3 = rp[l*4+3];
        int Wd = WW[l], Hh = HH[l], st = ST[l];
        #pragma unroll
        for (int p = 0; p < NPc; p++) {
            int fo = (l*NPc + p)*2;
            float lx = r0 + op[fo]   * 0.125f * r2;   // off/NP * 0.5
            float ly = r1 + op[fo+1] * 0.125f * r3;
            float x = lx * Wd - 0.5f;
            float y = ly * Hh - 0.5f;
            float wl = __shfl_sync(0xffffffffu, wgt, l*NPc + p);
            float x0f = floorf(x), y0f = floorf(y);
            int x0 = (int)x0f, y0 = (int)y0f;
            float fx = x - x0f, fy = y - y0f;
            float samp = 0.f;
            #pragma unroll
            for (int dy = 0; dy < 2; dy++) {
                #pragma unroll
                for (int dx = 0; dx < 2; dx++) {
                    int xi = x0 + dx, yi = y0 + dy;
                    if (xi >= 0 && xi < Wd && yi >= 0 && yi < Hh) {
                        float wc = (dx ? fx : 1.f-fx) * (dy ? fy : 1.f-fy);
                        samp += wc * value[((size_t)(st + yi*Wd + xi)*Bc + b)*Dc + h*DHc + lane];
                    }
                }
            }
            acc += wl * samp;
        }
    }
    out[(size_t)t*Dc + h*DHc + lane] = acc;
}

// ---------------- host launch ----------------
static void launch_gemm(const float* A, const float* W, const float* bias, float* C,
                        int M, int N, int K, bool relu = false) {
    dim3 grid((N + 63)/64, (M + 63)/64);
    if (relu) sgemm<1><<<grid, 256>>>(A, W, bias, C, M, N, K);
    else      sgemm<0><<<grid, 256>>>(A, W, bias, C, M, N, K);
}

extern "C" void kernel_launch(void* const* d_in, const int* in_sizes, int n_in,
                              void* d_out, int out_size) {
    const float* tgt      = (const float*)d_in[0];
    const float* pos      = (const float*)d_in[1];
    const float* refpts   = (const float*)d_in[2];
    const float* memory   = (const float*)d_in[3];
    const float* in_w     = (const float*)d_in[6];
    const float* in_b     = (const float*)d_in[7];
    const float* sa_ow    = (const float*)d_in[8];
    const float* sa_ob    = (const float*)d_in[9];
    const float* n1g      = (const float*)d_in[10];
    const float* n1b      = (const float*)d_in[11];
    const float* n2g      = (const float*)d_in[12];
    const float* n2b      = (const float*)d_in[13];
    const float* n3g      = (const float*)d_in[14];
    const float* n3b      = (const float*)d_in[15];
    const float* off_w    = (const float*)d_in[16];
    const float* off_b    = (const float*)d_in[17];
    const float* aw_w     = (const float*)d_in[18];
    const float* aw_b     = (const float*)d_in[19];
    const float* val_w    = (const float*)d_in[20];
    const float* val_b    = (const float*)d_in[21];
    const float* ca_ow    = (const float*)d_in[22];
    const float* ca_ob    = (const float*)d_in[23];
    const float* l1w      = (const float*)d_in[24];
    const float* l1b      = (const float*)d_in[25];
    const float* l2w      = (const float*)d_in[26];
    const float* l2b      = (const float*)d_in[27];
    float* out = (float*)d_out;

    float *p_qin, *p_q, *p_k, *p_v, *p_ao, *p_t1, *p_tgt2, *p_qca, *p_off, *p_aw, *p_ca, *p_tgt3, *p_ffn, *p_value;
    cudaGetSymbolAddress((void**)&p_qin,  g_qin);
    cudaGetSymbolAddress((void**)&p_q,    g_q);
    cudaGetSymbolAddress((void**)&p_k,    g_k);
    cudaGetSymbolAddress((void**)&p_v,    g_v);
    cudaGetSymbolAddress((void**)&p_ao,   g_ao);
    cudaGetSymbolAddress((void**)&p_t1,   g_t1);
    cudaGetSymbolAddress((void**)&p_tgt2, g_tgt2);
    cudaGetSymbolAddress((void**)&p_qca,  g_qca);
    cudaGetSymbolAddress((void**)&p_off,  g_off);
    cudaGetSymbolAddress((void**)&p_aw,   g_aw);
    cudaGetSymbolAddress((void**)&p_ca,   g_ca);
    cudaGetSymbolAddress((void**)&p_tgt3, g_tgt3);
    cudaGetSymbolAddress((void**)&p_ffn,  g_ffn);
    cudaGetSymbolAddress((void**)&p_value, g_value);

    const int n = Tc*Dc;

    // q_in = tgt + pos
    add_k<<<n/256, 256>>>(tgt, pos, p_qin, n);

    // QKV projections (q,k from tgt+pos; v from tgt)
    launch_gemm(p_qin, in_w,            in_b,       p_q, Tc, Dc, Dc);
    launch_gemm(p_qin, in_w + 256*256,  in_b + 256, p_k, Tc, Dc, Dc);
    launch_gemm(tgt,   in_w + 512*256,  in_b + 512, p_v, Tc, Dc, Dc);

    // fused self-attention
    attn_kernel<<<dim3(NQc/4, Hc, Bc), 128>>>(p_q, p_k, p_v, p_ao);

    // out proj + residual + LN(norm2)
    launch_gemm(p_ao, sa_ow, sa_ob, p_t1, Tc, Dc, Dc);
    residual_ln<<<Tc, 256>>>(tgt, p_t1, n2g, n2b, p_tgt2);

    // cross-attn query = tgt2 + pos
    add_k<<<n/256, 256>>>(p_tgt2, pos, p_qca, n);

    // value projection over memory (biggest GEMM)
    launch_gemm(memory, val_w, val_b, p_value, Sc*Bc, Dc, Dc);

    // sampling offsets + attention weights
    launch_gemm(p_qca, off_w, off_b, p_off, Tc, Dc, Dc);
    launch_gemm(p_qca, aw_w,  aw_b,  p_aw,  Tc, 128, Dc);

    // MS-deformable sampling
    deform_kernel<<<dim3(NQc, Bc), 256>>>(p_off, p_aw, refpts, p_value, p_ca);

    // cross-attn out proj + residual + LN(norm1)
    launch_gemm(p_ca, ca_ow, ca_ob, p_t1, Tc, Dc, Dc);
    residual_ln<<<Tc, 256>>>(p_tgt2, p_t1, n1g, n1b, p_tgt3);

    // FFN
    launch_gemm(p_tgt3, l1w, l1b, p_ffn, Tc, DFFc, Dc, /*relu=*/true);
    launch_gemm(p_ffn,  l2w, l2b, p_t1,  Tc, Dc, DFFc);
    residual_ln<<<Tc, 256>>>(p_tgt3, p_t1, n3g, n3b, out);
}

// round 3
// speedup vs baseline: 1.7327x; 1.7327x over previous
#include <cuda_runtime.h>
#include <cuda_bf16.h>
#include <cstdint>

#define NQc 900
#define Bc  8
#define Dc  256
#define Hc  8
#define DHc 32
#define NLc 4
#define NPc 4
#define DFFc 1024
#define Sc  19947
#define Tc  (NQc*Bc)        // 7200 tokens
#define BHc 64              // B*H batches

// ---------------- scratch (device globals; no allocation) ----------------
__device__ float g_qin [Tc*Dc];
__device__ float g_q   [BHc*NQc*DHc];   // [b*H+h][900][32]
__device__ float g_k   [BHc*NQc*DHc];
__device__ float g_v   [BHc*NQc*DHc];
__device__ float g_sc  [(size_t)BHc*NQc*NQc]; // scores [bh][900][900]
__device__ float g_ao  [Tc*Dc];
__device__ float g_t1  [Tc*Dc];
__device__ float g_tgt2[Tc*Dc];
__device__ float g_qca [Tc*Dc];
__device__ float g_off [Tc*Dc];
__device__ float g_aw  [Tc*128];
__device__ float g_ca  [Tc*Dc];
__device__ float g_tgt3[Tc*Dc];
__device__ float g_ffn [Tc*DFFc];
__device__ float g_value[(size_t)Sc*Bc*Dc];

// ---------------- elementwise add ----------------
__global__ void add_k(const float* __restrict__ a, const float* __restrict__ b,
                      float* __restrict__ c, int n) {
    int i = blockIdx.x*256 + threadIdx.x;
    if (i < n) c[i] = a[i] + b[i];
}

// ---------------- 128x128x8 double-buffered SGEMM ----------------
// C[M,N] = A[M,K] @ W[N,K]^T (+bias) ; optional batch via blockIdx.z strides.
// SCATTER=1: write C to [b*H+h][l][d] layout where row=l*8+b, col=h*32+d.
template<int RELU, int SCATTER>
__global__ __launch_bounds__(256, 2)
void sgemm128(const float* __restrict__ A, const float* __restrict__ W,
              const float* __restrict__ bias, float* __restrict__ C,
              int M, int N, int K, int aBatch, int wBatch, long long cBatch) {
    __shared__ float As[2][8][128];
    __shared__ float Ws[2][8][128];
    const float* Ab = A + (size_t)blockIdx.z * aBatch;
    const float* Wb = W + (size_t)blockIdx.z * wBatch;
    float* Cb = C + (size_t)blockIdx.z * cBatch;

    int tid = threadIdx.x;
    int tx = tid & 15, ty = tid >> 4;
    int row0 = blockIdx.y * 128, col0 = blockIdx.x * 128;

    int lr = tid >> 1;            // 0..127
    int lk = (tid & 1) * 4;       // 0 or 4
    bool aok = (row0 + lr) < M;
    bool wok = (col0 + lr) < N;
    const float* Aptr = Ab + (size_t)(row0 + lr) * K + lk;
    const float* Wptr = Wb + (size_t)(col0 + lr) * K + lk;

    float4 a4 = make_float4(0,0,0,0), w4 = make_float4(0,0,0,0);
    if (aok) a4 = *(const float4*)Aptr;
    if (wok) w4 = *(const float4*)Wptr;
    As[0][lk+0][lr]=a4.x; As[0][lk+1][lr]=a4.y; As[0][lk+2][lr]=a4.z; As[0][lk+3][lr]=a4.w;
    Ws[0][lk+0][lr]=w4.x; Ws[0][lk+1][lr]=w4.y; Ws[0][lk+2][lr]=w4.z; Ws[0][lk+3][lr]=w4.w;
    __syncthreads();

    float acc[8][8] = {};
    int nStages = K >> 3;
    int buf = 0;
    for (int s = 0; s < nStages; s++) {
        bool hasNext = (s + 1) < nStages;
        if (hasNext) {
            int k0 = (s + 1) << 3;
            a4 = make_float4(0,0,0,0); w4 = make_float4(0,0,0,0);
            if (aok) a4 = *(const float4*)(Aptr + k0);
            if (wok) w4 = *(const float4*)(Wptr + k0);
        }
        #pragma unroll
        for (int kk = 0; kk < 8; kk++) {
            float a[8], w[8];
            *(float4*)(&a[0]) = *(const float4*)(&As[buf][kk][ty*8]);
            *(float4*)(&a[4]) = *(const float4*)(&As[buf][kk][ty*8+4]);
            *(float4*)(&w[0]) = *(const float4*)(&Ws[buf][kk][tx*8]);
            *(float4*)(&w[4]) = *(const float4*)(&Ws[buf][kk][tx*8+4]);
            #pragma unroll
            for (int i = 0; i < 8; i++)
                #pragma unroll
                for (int j = 0; j < 8; j++)
                    acc[i][j] += a[i]*w[j];
        }
        if (hasNext) {
            buf ^= 1;
            As[buf][lk+0][lr]=a4.x; As[buf][lk+1][lr]=a4.y; As[buf][lk+2][lr]=a4.z; As[buf][lk+3][lr]=a4.w;
            Ws[buf][lk+0][lr]=w4.x; Ws[buf][lk+1][lr]=w4.y; Ws[buf][lk+2][lr]=w4.z; Ws[buf][lk+3][lr]=w4.w;
            __syncthreads();
        }
    }

    // epilogue
    #pragma unroll
    for (int i = 0; i < 8; i++) {
        int gr = row0 + ty*8 + i;
        if (gr >= M) continue;
        #pragma unroll
        for (int j4 = 0; j4 < 8; j4 += 4) {
            int gc = col0 + tx*8 + j4;
            if (gc + 3 >= N && gc >= N) continue;
            float4 o;
            o.x = acc[i][j4+0]; o.y = acc[i][j4+1]; o.z = acc[i][j4+2]; o.w = acc[i][j4+3];
            if (bias) {
                o.x += bias[gc+0]; o.y += bias[gc+1]; o.z += bias[gc+2]; o.w += bias[gc+3];
            }
            if (RELU) {
                o.x = fmaxf(o.x, 0.f); o.y = fmaxf(o.y, 0.f);
                o.z = fmaxf(o.z, 0.f); o.w = fmaxf(o.w, 0.f);
            }
            if (SCATTER) {
                int b = gr & 7, l = gr >> 3;
                int h = gc >> 5, d = gc & 31;
                *(float4*)(Cb + (((size_t)(b*Hc + h))*NQc + l)*DHc + d) = o;
            } else {
                *(float4*)(Cb + (size_t)gr*N + gc) = o;
            }
        }
    }
}

// ---------------- row softmax over scores [BHc*900][900], with 1/sqrt(32) fold ----------------
__global__ void softmax_rows(float* __restrict__ S) {
    int row = blockIdx.x*8 + (threadIdx.x >> 5);
    int lane = threadIdx.x & 31;
    float* p = S + (size_t)row * NQc;
    float mx = -1e30f;
    for (int j = lane; j < NQc; j += 32) mx = fmaxf(mx, p[j]);
    #pragma unroll
    for (int o = 16; o; o >>= 1) mx = fmaxf(mx, __shfl_xor_sync(0xffffffffu, mx, o));
    float s = 0.f;
    for (int j = lane; j < NQc; j += 32) {
        float e = __expf((p[j] - mx) * 0.17677669529663689f);
        p[j] = e; s += e;
    }
    #pragma unroll
    for (int o = 16; o; o >>= 1) s += __shfl_xor_sync(0xffffffffu, s, o);
    float inv = 1.f / s;
    for (int j = lane; j < NQc; j += 32) p[j] *= inv;
}

// ---------------- AV: O[l,b,D] slice = P[bh][900,900] @ V[bh][900,32] ----------------
__global__ __launch_bounds__(256, 2)
void av_kernel(const float* __restrict__ P, const float* __restrict__ V,
               float* __restrict__ O) {
    __shared__ float Pt[128][36];
    __shared__ float Vt[32][36];
    int z = blockIdx.y;
    int row0 = blockIdx.x * 128;
    int b = z >> 3, h = z & 7;
    const float* Pb = P + (size_t)z * NQc * NQc;
    const float* Vb = V + (size_t)z * NQc * DHc;
    int tid = threadIdx.x, w = tid >> 5, lane = tid & 31;

    int pr = tid >> 1, pk = (tid & 1) * 16;
    int vr = tid >> 3, vd = (tid & 7) * 4;
    bool prow = (row0 + pr) < NQc;

    float acc[16] = {};
    for (int k0 = 0; k0 < NQc; k0 += 32) {
        #pragma unroll
        for (int q = 0; q < 4; q++) {
            int kk = pk + q*4;
            float4 v4 = (prow && (k0 + kk) < NQc)
                ? *(const float4*)(Pb + (size_t)(row0 + pr)*NQc + k0 + kk)
                : make_float4(0,0,0,0);
            *(float4*)(&Pt[pr][kk]) = v4;
        }
        {
            float4 v4 = ((k0 + vr) < NQc)
                ? *(const float4*)(Vb + (size_t)(k0 + vr)*DHc + vd)
                : make_float4(0,0,0,0);
            *(float4*)(&Vt[vr][vd]) = v4;
        }
        __syncthreads();
        #pragma unroll
        for (int k4 = 0; k4 < 8; k4++) {
            float v0 = Vt[k4*4+0][lane];
            float v1 = Vt[k4*4+1][lane];
            float v2 = Vt[k4*4+2][lane];
            float v3 = Vt[k4*4+3][lane];
            #pragma unroll
            for (int i = 0; i < 16; i++) {
                float4 pb = *(const float4*)(&Pt[w*16 + i][k4*4]);
                acc[i] += pb.x*v0;
                acc[i] += pb.y*v1;
                acc[i] += pb.z*v2;
                acc[i] += pb.w*v3;
            }
        }
        __syncthreads();
    }
    #pragma unroll
    for (int i = 0; i < 16; i++) {
        int row = row0 + w*16 + i;
        if (row < NQc)
            O[((size_t)row*Bc + b)*Dc + h*DHc + lane] = acc[i];
    }
}

// ---------------- residual + LayerNorm ----------------
__global__ void residual_ln(const float* __restrict__ res, const float* __restrict__ x,
                            const float* __restrict__ g, const float* __restrict__ be,
                            float* __restrict__ out) {
    int t = blockIdx.x, i = threadIdx.x;
    float v = res[(size_t)t*Dc + i] + x[(size_t)t*Dc + i];
    __shared__ float red[8];
    __shared__ float mean_s, rstd_s;
    float s = v;
    #pragma unroll
    for (int o = 16; o; o >>= 1) s += __shfl_xor_sync(0xffffffffu, s, o);
    if ((i & 31) == 0) red[i >> 5] = s;
    __syncthreads();
    if (i < 32) {
        float t2 = (i < 8) ? red[i] : 0.f;
        #pragma unroll
        for (int o = 4; o; o >>= 1) t2 += __shfl_xor_sync(0xffffffffu, t2, o);
        if (i == 0) mean_s = t2 * (1.f/Dc);
    }
    __syncthreads();
    float m = mean_s;
    float d = v - m;
    float sq = d*d;
    #pragma unroll
    for (int o = 16; o; o >>= 1) sq += __shfl_xor_sync(0xffffffffu, sq, o);
    if ((i & 31) == 0) red[i >> 5] = sq;
    __syncthreads();
    if (i < 32) {
        float t2 = (i < 8) ? red[i] : 0.f;
        #pragma unroll
        for (int o = 4; o; o >>= 1) t2 += __shfl_xor_sync(0xffffffffu, t2, o);
        if (i == 0) rstd_s = rsqrtf(t2 * (1.f/Dc) + 1e-5f);
    }
    __syncthreads();
    out[(size_t)t*Dc + i] = d * rstd_s * g[i] + be[i];
}

// ---------------- MS-deformable attention sampling ----------------
__global__ void deform_kernel(const float* __restrict__ off, const float* __restrict__ aw,
                              const float* __restrict__ ref, const float* __restrict__ value,
                              float* __restrict__ out) {
    int q = blockIdx.x, b = blockIdx.y;
    int t = q*Bc + b;
    int tid = threadIdx.x, h = tid >> 5, lane = tid & 31;

    float a = (lane < 16) ? aw[(size_t)t*128 + h*16 + lane] : -1e30f;
    float mx = a;
    #pragma unroll
    for (int o = 16; o; o >>= 1) mx = fmaxf(mx, __shfl_xor_sync(0xffffffffu, mx, o));
    float e = (lane < 16) ? __expf(a - mx) : 0.f;
    float s = e;
    #pragma unroll
    for (int o = 16; o; o >>= 1) s += __shfl_xor_sync(0xffffffffu, s, o);
    float wgt = e / s;

    const float* rp = ref + (size_t)t*(NLc*4);
    const float* op = off + (size_t)t*Dc + h*32;
    const int HH[4] = {100,50,25,13};
    const int WW[4] = {150,75,38,19};
    const int ST[4] = {0,15000,18750,19700};
    float acc = 0.f;
    #pragma unroll
    for (int l = 0; l < NLc; l++) {
        float r0 = rp[l*4+0], r1 = rp[l*4+1], r2 = rp[l*4+2], r3 = rp[l*4+3];
        int Wd = WW[l], Hh = HH[l], st = ST[l];
        #pragma unroll
        for (int p = 0; p < NPc; p++) {
            int fo = (l*NPc + p)*2;
            float lx = r0 + op[fo]   * 0.125f * r2;
            float ly = r1 + op[fo+1] * 0.125f * r3;
            float x = lx * Wd - 0.5f;
            float y = ly * Hh - 0.5f;
            float wl = __shfl_sync(0xffffffffu, wgt, l*NPc + p);
            float x0f = floorf(x), y0f = floorf(y);
            int x0 = (int)x0f, y0 = (int)y0f;
            float fx = x - x0f, fy = y - y0f;
            float samp = 0.f;
            #pragma unroll
            for (int dy = 0; dy < 2; dy++) {
                #pragma unroll
                for (int dx = 0; dx < 2; dx++) {
                    int xi = x0 + dx, yi = y0 + dy;
                    if (xi >= 0 && xi < Wd && yi >= 0 && yi < Hh) {
                        float wc = (dx ? fx : 1.f-fx) * (dy ? fy : 1.f-fy);
                        samp += wc * value[((size_t)(st + yi*Wd + xi)*Bc + b)*Dc + h*DHc + lane];
                    }
                }
            }
            acc += wl * samp;
        }
    }
    out[(size_t)t*Dc + h*DHc + lane] = acc;
}

// ---------------- host helpers ----------------
static void launch_gemm(const float* A, const float* W, const float* bias, float* C,
                        int M, int N, int K, bool relu = false) {
    dim3 grid((N + 127)/128, (M + 127)/128, 1);
    if (relu) sgemm128<1,0><<<grid, 256>>>(A, W, bias, C, M, N, K, 0, 0, 0);
    else      sgemm128<0,0><<<grid, 256>>>(A, W, bias, C, M, N, K, 0, 0, 0);
}
static void launch_gemm_scatter(const float* A, const float* W, const float* bias, float* C,
                                int M, int N, int K) {
    dim3 grid((N + 127)/128, (M + 127)/128, 1);
    sgemm128<0,1><<<grid, 256>>>(A, W, bias, C, M, N, K, 0, 0, 0);
}

extern "C" void kernel_launch(void* const* d_in, const int* in_sizes, int n_in,
                              void* d_out, int out_size) {
    const float* tgt      = (const float*)d_in[0];
    const float* pos      = (const float*)d_in[1];
    const float* refpts   = (const float*)d_in[2];
    const float* memory   = (const float*)d_in[3];
    const float* in_w     = (const float*)d_in[6];
    const float* in_b     = (const float*)d_in[7];
    const float* sa_ow    = (const float*)d_in[8];
    const float* sa_ob    = (const float*)d_in[9];
    const float* n1g      = (const float*)d_in[10];
    const float* n1b      = (const float*)d_in[11];
    const float* n2g      = (const float*)d_in[12];
    const float* n2b      = (const float*)d_in[13];
    const float* n3g      = (const float*)d_in[14];
    const float* n3b      = (const float*)d_in[15];
    const float* off_w    = (const float*)d_in[16];
    const float* off_b    = (const float*)d_in[17];
    const float* aw_w     = (const float*)d_in[18];
    const float* aw_b     = (const float*)d_in[19];
    const float* val_w    = (const float*)d_in[20];
    const float* val_b    = (const float*)d_in[21];
    const float* ca_ow    = (const float*)d_in[22];
    const float* ca_ob    = (const float*)d_in[23];
    const float* l1w      = (const float*)d_in[24];
    const float* l1b      = (const float*)d_in[25];
    const float* l2w      = (const float*)d_in[26];
    const float* l2b      = (const float*)d_in[27];
    float* out = (float*)d_out;

    float *p_qin, *p_q, *p_k, *p_v, *p_sc, *p_ao, *p_t1, *p_tgt2, *p_qca,
          *p_off, *p_aw, *p_ca, *p_tgt3, *p_ffn, *p_value;
    cudaGetSymbolAddress((void**)&p_qin,  g_qin);
    cudaGetSymbolAddress((void**)&p_q,    g_q);
    cudaGetSymbolAddress((void**)&p_k,    g_k);
    cudaGetSymbolAddress((void**)&p_v,    g_v);
    cudaGetSymbolAddress((void**)&p_sc,   g_sc);
    cudaGetSymbolAddress((void**)&p_ao,   g_ao);
    cudaGetSymbolAddress((void**)&p_t1,   g_t1);
    cudaGetSymbolAddress((void**)&p_tgt2, g_tgt2);
    cudaGetSymbolAddress((void**)&p_qca,  g_qca);
    cudaGetSymbolAddress((void**)&p_off,  g_off);
    cudaGetSymbolAddress((void**)&p_aw,   g_aw);
    cudaGetSymbolAddress((void**)&p_ca,   g_ca);
    cudaGetSymbolAddress((void**)&p_tgt3, g_tgt3);
    cudaGetSymbolAddress((void**)&p_ffn,  g_ffn);
    cudaGetSymbolAddress((void**)&p_value, g_value);

    const int n = Tc*Dc;

    // q_in = tgt + pos
    add_k<<<n/256, 256>>>(tgt, pos, p_qin, n);

    // QKV projections -> [b,h,l,d]
    launch_gemm_scatter(p_qin, in_w,            in_b,       p_q, Tc, Dc, Dc);
    launch_gemm_scatter(p_qin, in_w + 256*256,  in_b + 256, p_k, Tc, Dc, Dc);
    launch_gemm_scatter(tgt,   in_w + 512*256,  in_b + 512, p_v, Tc, Dc, Dc);

    // scores: batched [bh] 900x900x32
    {
        dim3 grid((NQc + 127)/128, (NQc + 127)/128, BHc);
        sgemm128<0,0><<<grid, 256>>>(p_q, p_k, nullptr, p_sc,
                                     NQc, NQc, DHc,
                                     NQc*DHc, NQc*DHc, (long long)NQc*NQc);
    }
    // softmax rows
    softmax_rows<<<BHc*NQc/8, 256>>>(p_sc);
    // O = P V  -> [l,b,D]
    av_kernel<<<dim3((NQc + 127)/128, BHc), 256>>>(p_sc, p_v, p_ao);

    // out proj + residual + LN(norm2)
    launch_gemm(p_ao, sa_ow, sa_ob, p_t1, Tc, Dc, Dc);
    residual_ln<<<Tc, 256>>>(tgt, p_t1, n2g, n2b, p_tgt2);

    // cross-attn query = tgt2 + pos
    add_k<<<n/256, 256>>>(p_tgt2, pos, p_qca, n);

    // value projection over memory (biggest GEMM)
    launch_gemm(memory, val_w, val_b, p_value, Sc*Bc, Dc, Dc);

    // sampling offsets + attention weights
    launch_gemm(p_qca, off_w, off_b, p_off, Tc, Dc, Dc);
    launch_gemm(p_qca, aw_w,  aw_b,  p_aw,  Tc, 128, Dc);

    // MS-deformable sampling
    deform_kernel<<<dim3(NQc, Bc), 256>>>(p_off, p_aw, refpts, p_value, p_ca);

    // cross-attn out proj + residual + LN(norm1)
    launch_gemm(p_ca, ca_ow, ca_ob, p_t1, Tc, Dc, Dc);
    residual_ln<<<Tc, 256>>>(p_tgt2, p_t1, n1g, n1b, p_tgt3);

    // FFN
    launch_gemm(p_tgt3, l1w, l1b, p_ffn, Tc, DFFc, Dc, /*relu=*/true);
    launch_gemm(p_ffn,  l2w, l2b, p_t1,  Tc, Dc, DFFc);
    residual_ln<<<Tc, 256>>>(p_tgt3, p_t1, n3g, n3b, out);
}

// round 5
// speedup vs baseline: 2.7557x; 1.5904x over previous
#include <cuda_runtime.h>
#include <cuda_bf16.h>
#include <cstdint>

#define NQc 900
#define Bc  8
#define Dc  256
#define Hc  8
#define DHc 32
#define NLc 4
#define NPc 4
#define DFFc 1024
#define Sc  19947
#define Tc  (NQc*Bc)        // 7200 tokens
#define BHc 64              // B*H batches

// ---------------- scratch (device globals; no allocation) ----------------
__device__ float g_qin [Tc*Dc];
__device__ float g_q   [BHc*NQc*DHc];   // [b*H+h][900][32]
__device__ float g_k   [BHc*NQc*DHc];
__device__ float g_v   [BHc*NQc*DHc];
__device__ float g_sc  [(size_t)BHc*NQc*NQc]; // scores [bh][900][900]
__device__ float g_ao  [Tc*Dc];
__device__ float g_t1  [Tc*Dc];
__device__ float g_tgt2[Tc*Dc];
__device__ float g_qca [Tc*Dc];
__device__ float g_off [Tc*Dc];
__device__ float g_aw  [Tc*128];
__device__ float g_ca  [Tc*Dc];
__device__ float g_tgt3[Tc*Dc];
__device__ float g_ffn [Tc*DFFc];
__device__ float g_value[(size_t)Sc*Bc*Dc];

// ---------------- elementwise add ----------------
__global__ void add_k(const float* __restrict__ a, const float* __restrict__ b,
                      float* __restrict__ c, int n) {
    int i = blockIdx.x*256 + threadIdx.x;
    if (i < n) c[i] = a[i] + b[i];
}

// ================= split-bf16 tensor-core GEMM =================
// C[M,N] = A[M,K] @ W[N,K]^T + bias, fp32 in/out, 3-pass bf16 split.
// Block 128x128, BK=32 per stage, 8 warps (2x4), warp tile 64x32.
// SCATTER=1: C row=l*8+b, col=h*32+d -> [b*H+h][l][d].

__device__ __forceinline__ void mma16816(float& d0, float& d1, float& d2, float& d3,
                                         uint32_t a0, uint32_t a1, uint32_t a2, uint32_t a3,
                                         uint32_t b0, uint32_t b1) {
    asm volatile(
        "mma.sync.aligned.m16n8k16.row.col.f32.bf16.bf16.f32 "
        "{%0,%1,%2,%3},{%4,%5,%6,%7},{%8,%9},{%0,%1,%2,%3};\n"
        : "+f"(d0), "+f"(d1), "+f"(d2), "+f"(d3)
        : "r"(a0), "r"(a1), "r"(a2), "r"(a3), "r"(b0), "r"(b1));
}

// split one float into hi (truncated bf16) and residual
__device__ __forceinline__ void split2(float f0, float f1, uint32_t& hi, uint32_t& lo) {
    uint32_t u0 = __float_as_uint(f0) & 0xFFFF0000u;
    uint32_t u1 = __float_as_uint(f1) & 0xFFFF0000u;
    hi = (u0 >> 16) | u1;                  // low half = f0's bf16, high = f1's
    float r0 = f0 - __uint_as_float(u0);
    float r1 = f1 - __uint_as_float(u1);
    __nv_bfloat162 l = __floats2bfloat162_rn(r0, r1);
    lo = *reinterpret_cast<uint32_t*>(&l);
}

#define SWSTR 20   // words per row (16 used + 4 pad) -> conflict-free fragments

template<int RELU, int SCATTER>
__global__ __launch_bounds__(256)
void bgemm(const float* __restrict__ A, const float* __restrict__ W,
           const float* __restrict__ bias, float* __restrict__ C,
           int M, int N, int K) {
    // sw[0]=A_hi sw[1]=A_lo sw[2]=B_hi sw[3]=B_lo
    __shared__ uint32_t sw[4][128][SWSTR];

    int tid = threadIdx.x;
    int warp = tid >> 5, lane = tid & 31;
    int g = lane >> 2, tg = lane & 3;
    int wm = warp >> 2, wn = warp & 3;
    int row0 = blockIdx.y * 128, col0 = blockIdx.x * 128;

    // loader mapping: row r = tid/2, half = tid&1 covers k 0..15 / 16..31
    int lr = tid >> 1, half = tid & 1;
    bool aok = (row0 + lr) < M;           // all N are multiples of 128 -> B always ok
    const float* Aptr = A + (size_t)(row0 + lr) * K + half * 16;
    const float* Wptr = W + (size_t)(col0 + lr) * K + half * 16;

    float4 pa[4], pb[4];
    #pragma unroll
    for (int q = 0; q < 4; q++) {
        pa[q] = aok ? *(const float4*)(Aptr + q*4) : make_float4(0,0,0,0);
        pb[q] = *(const float4*)(Wptr + q*4);
    }

    float acc[4][4][4];
    #pragma unroll
    for (int i = 0; i < 4; i++)
        #pragma unroll
        for (int j = 0; j < 4; j++)
            #pragma unroll
            for (int e = 0; e < 4; e++) acc[i][j][e] = 0.f;

    int nStages = K >> 5;
    for (int s = 0; s < nStages; s++) {
        // convert + store current chunk
        #pragma unroll
        for (int q = 0; q < 4; q++) {
            int c = half*8 + q*2;
            uint32_t h0, l0, h1, l1;
            split2(pa[q].x, pa[q].y, h0, l0);
            split2(pa[q].z, pa[q].w, h1, l1);
            sw[0][lr][c]   = h0; sw[0][lr][c+1] = h1;
            sw[1][lr][c]   = l0; sw[1][lr][c+1] = l1;
            split2(pb[q].x, pb[q].y, h0, l0);
            split2(pb[q].z, pb[q].w, h1, l1);
            sw[2][lr][c]   = h0; sw[2][lr][c+1] = h1;
            sw[3][lr][c]   = l0; sw[3][lr][c+1] = l1;
        }
        __syncthreads();

        // prefetch next chunk
        if (s + 1 < nStages) {
            int k0 = (s + 1) << 5;
            #pragma unroll
            for (int q = 0; q < 4; q++) {
                pa[q] = aok ? *(const float4*)(Aptr + k0 + q*4) : make_float4(0,0,0,0);
                pb[q] = *(const float4*)(Wptr + k0 + q*4);
            }
        }

        // two k16 substeps
        #pragma unroll
        for (int ks = 0; ks < 2; ks++) {
            int cb = ks * 8;
            uint32_t bh[4][2], bl[4][2];
            #pragma unroll
            for (int j = 0; j < 4; j++) {
                int rB = wn*32 + j*8 + g;
                bh[j][0] = sw[2][rB][cb + tg];
                bh[j][1] = sw[2][rB][cb + tg + 4];
                bl[j][0] = sw[3][rB][cb + tg];
                bl[j][1] = sw[3][rB][cb + tg + 4];
            }
            #pragma unroll
            for (int i = 0; i < 4; i++) {
                int rA = wm*64 + i*16 + g;
                uint32_t ah0 = sw[0][rA][cb + tg];
                uint32_t ah1 = sw[0][rA+8][cb + tg];
                uint32_t ah2 = sw[0][rA][cb + tg + 4];
                uint32_t ah3 = sw[0][rA+8][cb + tg + 4];
                uint32_t al0 = sw[1][rA][cb + tg];
                uint32_t al1 = sw[1][rA+8][cb + tg];
                uint32_t al2 = sw[1][rA][cb + tg + 4];
                uint32_t al3 = sw[1][rA+8][cb + tg + 4];
                #pragma unroll
                for (int j = 0; j < 4; j++) {
                    float* d = acc[i][j];
                    mma16816(d[0],d[1],d[2],d[3], ah0,ah1,ah2,ah3, bh[j][0],bh[j][1]);
                    mma16816(d[0],d[1],d[2],d[3], ah0,ah1,ah2,ah3, bl[j][0],bl[j][1]);
                    mma16816(d[0],d[1],d[2],d[3], al0,al1,al2,al3, bh[j][0],bh[j][1]);
                }
            }
        }
        __syncthreads();
    }

    // epilogue
    #pragma unroll
    for (int i = 0; i < 4; i++) {
        int r0 = row0 + wm*64 + i*16 + g;
        int r1 = r0 + 8;
        #pragma unroll
        for (int j = 0; j < 4; j++) {
            int c = col0 + wn*32 + j*8 + tg*2;
            float bx = bias ? bias[c] : 0.f;
            float by = bias ? bias[c+1] : 0.f;
            float v0 = acc[i][j][0] + bx, v1 = acc[i][j][1] + by;
            float v2 = acc[i][j][2] + bx, v3 = acc[i][j][3] + by;
            if (RELU) {
                v0 = fmaxf(v0, 0.f); v1 = fmaxf(v1, 0.f);
                v2 = fmaxf(v2, 0.f); v3 = fmaxf(v3, 0.f);
            }
            if (SCATTER) {
                int h = c >> 5, d = c & 31;
                if (r0 < M) {
                    int b = r0 & 7, l = r0 >> 3;
                    *(float2*)(C + (((size_t)(b*Hc + h))*NQc + l)*DHc + d) = make_float2(v0, v1);
                }
                if (r1 < M) {
                    int b = r1 & 7, l = r1 >> 3;
                    *(float2*)(C + (((size_t)(b*Hc + h))*NQc + l)*DHc + d) = make_float2(v2, v3);
                }
            } else {
                if (r0 < M) *(float2*)(C + (size_t)r0*N + c) = make_float2(v0, v1);
                if (r1 < M) *(float2*)(C + (size_t)r1*N + c) = make_float2(v2, v3);
            }
        }
    }
}

// ---------------- fp32 SGEMM kept for batched scores ----------------
__global__ __launch_bounds__(256, 2)
void sgemm128(const float* __restrict__ A, const float* __restrict__ W,
              float* __restrict__ C,
              int M, int N, int K, int aBatch, int wBatch, long long cBatch) {
    __shared__ float As[2][8][128];
    __shared__ float Ws[2][8][128];
    const float* Ab = A + (size_t)blockIdx.z * aBatch;
    const float* Wb = W + (size_t)blockIdx.z * wBatch;
    float* Cb = C + (size_t)blockIdx.z * cBatch;

    int tid = threadIdx.x;
    int tx = tid & 15, ty = tid >> 4;
    int row0 = blockIdx.y * 128, col0 = blockIdx.x * 128;

    int lr = tid >> 1;
    int lk = (tid & 1) * 4;
    bool aok = (row0 + lr) < M;
    bool wok = (col0 + lr) < N;
    const float* Aptr = Ab + (size_t)(row0 + lr) * K + lk;
    const float* Wptr = Wb + (size_t)(col0 + lr) * K + lk;

    float4 a4 = make_float4(0,0,0,0), w4 = make_float4(0,0,0,0);
    if (aok) a4 = *(const float4*)Aptr;
    if (wok) w4 = *(const float4*)Wptr;
    As[0][lk+0][lr]=a4.x; As[0][lk+1][lr]=a4.y; As[0][lk+2][lr]=a4.z; As[0][lk+3][lr]=a4.w;
    Ws[0][lk+0][lr]=w4.x; Ws[0][lk+1][lr]=w4.y; Ws[0][lk+2][lr]=w4.z; Ws[0][lk+3][lr]=w4.w;
    __syncthreads();

    float acc[8][8] = {};
    int nStages = K >> 3;
    int buf = 0;
    for (int s = 0; s < nStages; s++) {
        bool hasNext = (s + 1) < nStages;
        if (hasNext) {
            int k0 = (s + 1) << 3;
            a4 = make_float4(0,0,0,0); w4 = make_float4(0,0,0,0);
            if (aok) a4 = *(const float4*)(Aptr + k0);
            if (wok) w4 = *(const float4*)(Wptr + k0);
        }
        #pragma unroll
        for (int kk = 0; kk < 8; kk++) {
            float a[8], w[8];
            *(float4*)(&a[0]) = *(const float4*)(&As[buf][kk][ty*8]);
            *(float4*)(&a[4]) = *(const float4*)(&As[buf][kk][ty*8+4]);
            *(float4*)(&w[0]) = *(const float4*)(&Ws[buf][kk][tx*8]);
            *(float4*)(&w[4]) = *(const float4*)(&Ws[buf][kk][tx*8+4]);
            #pragma unroll
            for (int i = 0; i < 8; i++)
                #pragma unroll
                for (int j = 0; j < 8; j++)
                    acc[i][j] += a[i]*w[j];
        }
        if (hasNext) {
            buf ^= 1;
            As[buf][lk+0][lr]=a4.x; As[buf][lk+1][lr]=a4.y; As[buf][lk+2][lr]=a4.z; As[buf][lk+3][lr]=a4.w;
            Ws[buf][lk+0][lr]=w4.x; Ws[buf][lk+1][lr]=w4.y; Ws[buf][lk+2][lr]=w4.z; Ws[buf][lk+3][lr]=w4.w;
            __syncthreads();
        }
    }

    #pragma unroll
    for (int i = 0; i < 8; i++) {
        int gr = row0 + ty*8 + i;
        if (gr >= M) continue;
        #pragma unroll
        for (int j4 = 0; j4 < 8; j4 += 4) {
            int gc = col0 + tx*8 + j4;
            if (gc >= N) continue;
            float4 o;
            o.x = acc[i][j4+0]; o.y = acc[i][j4+1]; o.z = acc[i][j4+2]; o.w = acc[i][j4+3];
            *(float4*)(Cb + (size_t)gr*N + gc) = o;
        }
    }
}

// ---------------- row softmax over scores [BHc*900][900], with 1/sqrt(32) fold ----------------
__global__ void softmax_rows(float* __restrict__ S) {
    int row = blockIdx.x*8 + (threadIdx.x >> 5);
    int lane = threadIdx.x & 31;
    float* p = S + (size_t)row * NQc;
    float mx = -1e30f;
    for (int j = lane; j < NQc; j += 32) mx = fmaxf(mx, p[j]);
    #pragma unroll
    for (int o = 16; o; o >>= 1) mx = fmaxf(mx, __shfl_xor_sync(0xffffffffu, mx, o));
    float s = 0.f;
    for (int j = lane; j < NQc; j += 32) {
        float e = __expf((p[j] - mx) * 0.17677669529663689f);
        p[j] = e; s += e;
    }
    #pragma unroll
    for (int o = 16; o; o >>= 1) s += __shfl_xor_sync(0xffffffffu, s, o);
    float inv = 1.f / s;
    for (int j = lane; j < NQc; j += 32) p[j] *= inv;
}

// ---------------- AV: O[l,b,D] slice = P[bh][900,900] @ V[bh][900,32] ----------------
__global__ __launch_bounds__(256, 2)
void av_kernel(const float* __restrict__ P, const float* __restrict__ V,
               float* __restrict__ O) {
    __shared__ float Pt[128][36];
    __shared__ float Vt[32][36];
    int z = blockIdx.y;
    int row0 = blockIdx.x * 128;
    int b = z >> 3, h = z & 7;
    const float* Pb = P + (size_t)z * NQc * NQc;
    const float* Vb = V + (size_t)z * NQc * DHc;
    int tid = threadIdx.x, w = tid >> 5, lane = tid & 31;

    int pr = tid >> 1, pk = (tid & 1) * 16;
    int vr = tid >> 3, vd = (tid & 7) * 4;
    bool prow = (row0 + pr) < NQc;

    float acc[16] = {};
    for (int k0 = 0; k0 < NQc; k0 += 32) {
        #pragma unroll
        for (int q = 0; q < 4; q++) {
            int kk = pk + q*4;
            float4 v4 = (prow && (k0 + kk) < NQc)
                ? *(const float4*)(Pb + (size_t)(row0 + pr)*NQc + k0 + kk)
                : make_float4(0,0,0,0);
            *(float4*)(&Pt[pr][kk]) = v4;
        }
        {
            float4 v4 = ((k0 + vr) < NQc)
                ? *(const float4*)(Vb + (size_t)(k0 + vr)*DHc + vd)
                : make_float4(0,0,0,0);
            *(float4*)(&Vt[vr][vd]) = v4;
        }
        __syncthreads();
        #pragma unroll
        for (int k4 = 0; k4 < 8; k4++) {
            float v0 = Vt[k4*4+0][lane];
            float v1 = Vt[k4*4+1][lane];
            float v2 = Vt[k4*4+2][lane];
            float v3 = Vt[k4*4+3][lane];
            #pragma unroll
            for (int i = 0; i < 16; i++) {
                float4 pb = *(const float4*)(&Pt[w*16 + i][k4*4]);
                acc[i] += pb.x*v0;
                acc[i] += pb.y*v1;
                acc[i] += pb.z*v2;
                acc[i] += pb.w*v3;
            }
        }
        __syncthreads();
    }
    #pragma unroll
    for (int i = 0; i < 16; i++) {
        int row = row0 + w*16 + i;
        if (row < NQc)
            O[((size_t)row*Bc + b)*Dc + h*DHc + lane] = acc[i];
    }
}

// ---------------- residual + LayerNorm ----------------
__global__ void residual_ln(const float* __restrict__ res, const float* __restrict__ x,
                            const float* __restrict__ g, const float* __restrict__ be,
                            float* __restrict__ out) {
    int t = blockIdx.x, i = threadIdx.x;
    float v = res[(size_t)t*Dc + i] + x[(size_t)t*Dc + i];
    __shared__ float red[8];
    __shared__ float mean_s, rstd_s;
    float s = v;
    #pragma unroll
    for (int o = 16; o; o >>= 1) s += __shfl_xor_sync(0xffffffffu, s, o);
    if ((i & 31) == 0) red[i >> 5] = s;
    __syncthreads();
    if (i < 32) {
        float t2 = (i < 8) ? red[i] : 0.f;
        #pragma unroll
        for (int o = 4; o; o >>= 1) t2 += __shfl_xor_sync(0xffffffffu, t2, o);
        if (i == 0) mean_s = t2 * (1.f/Dc);
    }
    __syncthreads();
    float m = mean_s;
    float d = v - m;
    float sq = d*d;
    #pragma unroll
    for (int o = 16; o; o >>= 1) sq += __shfl_xor_sync(0xffffffffu, sq, o);
    if ((i & 31) == 0) red[i >> 5] = sq;
    __syncthreads();
    if (i < 32) {
        float t2 = (i < 8) ? red[i] : 0.f;
        #pragma unroll
        for (int o = 4; o; o >>= 1) t2 += __shfl_xor_sync(0xffffffffu, t2, o);
        if (i == 0) rstd_s = rsqrtf(t2 * (1.f/Dc) + 1e-5f);
    }
    __syncthreads();
    out[(size_t)t*Dc + i] = d * rstd_s * g[i] + be[i];
}

// ---------------- MS-deformable attention sampling ----------------
__global__ void deform_kernel(const float* __restrict__ off, const float* __restrict__ aw,
                              const float* __restrict__ ref, const float* __restrict__ value,
                              float* __restrict__ out) {
    int q = blockIdx.x, b = blockIdx.y;
    int t = q*Bc + b;
    int tid = threadIdx.x, h = tid >> 5, lane = tid & 31;

    float a = (lane < 16) ? aw[(size_t)t*128 + h*16 + lane] : -1e30f;
    float mx = a;
    #pragma unroll
    for (int o = 16; o; o >>= 1) mx = fmaxf(mx, __shfl_xor_sync(0xffffffffu, mx, o));
    float e = (lane < 16) ? __expf(a - mx) : 0.f;
    float s = e;
    #pragma unroll
    for (int o = 16; o; o >>= 1) s += __shfl_xor_sync(0xffffffffu, s, o);
    float wgt = e / s;

    const float* rp = ref + (size_t)t*(NLc*4);
    const float* op = off + (size_t)t*Dc + h*32;
    const int HH[4] = {100,50,25,13};
    const int WW[4] = {150,75,38,19};
    const int ST[4] = {0,15000,18750,19700};
    float acc = 0.f;
    #pragma unroll
    for (int l = 0; l < NLc; l++) {
        float r0 = rp[l*4+0], r1 = rp[l*4+1], r2 = rp[l*4+2], r3 = rp[l*4+3];
        int Wd = WW[l], Hh = HH[l], st = ST[l];
        #pragma unroll
        for (int p = 0; p < NPc; p++) {
            int fo = (l*NPc + p)*2;
            float lx = r0 + op[fo]   * 0.125f * r2;
            float ly = r1 + op[fo+1] * 0.125f * r3;
            float x = lx * Wd - 0.5f;
            float y = ly * Hh - 0.5f;
            float wl = __shfl_sync(0xffffffffu, wgt, l*NPc + p);
            float x0f = floorf(x), y0f = floorf(y);
            int x0 = (int)x0f, y0 = (int)y0f;
            float fx = x - x0f, fy = y - y0f;
            float samp = 0.f;
            #pragma unroll
            for (int dy = 0; dy < 2; dy++) {
                #pragma unroll
                for (int dx = 0; dx < 2; dx++) {
                    int xi = x0 + dx, yi = y0 + dy;
                    if (xi >= 0 && xi < Wd && yi >= 0 && yi < Hh) {
                        float wc = (dx ? fx : 1.f-fx) * (dy ? fy : 1.f-fy);
                        samp += wc * value[((size_t)(st + yi*Wd + xi)*Bc + b)*Dc + h*DHc + lane];
                    }
                }
            }
            acc += wl * samp;
        }
    }
    out[(size_t)t*Dc + h*DHc + lane] = acc;
}

// ---------------- host helpers ----------------
static void launch_bgemm(const float* A, const float* W, const float* bias, float* C,
                         int M, int N, int K, bool relu, bool scatter) {
    dim3 grid(N/128, (M + 127)/128);
    if (scatter)      bgemm<0,1><<<grid, 256>>>(A, W, bias, C, M, N, K);
    else if (relu)    bgemm<1,0><<<grid, 256>>>(A, W, bias, C, M, N, K);
    else              bgemm<0,0><<<grid, 256>>>(A, W, bias, C, M, N, K);
}

extern "C" void kernel_launch(void* const* d_in, const int* in_sizes, int n_in,
                              void* d_out, int out_size) {
    const float* tgt      = (const float*)d_in[0];
    const float* pos      = (const float*)d_in[1];
    const float* refpts   = (const float*)d_in[2];
    const float* memory   = (const float*)d_in[3];
    const float* in_w     = (const float*)d_in[6];
    const float* in_b     = (const float*)d_in[7];
    const float* sa_ow    = (const float*)d_in[8];
    const float* sa_ob    = (const float*)d_in[9];
    const float* n1g      = (const float*)d_in[10];
    const float* n1b      = (const float*)d_in[11];
    const float* n2g      = (const float*)d_in[12];
    const float* n2b      = (const float*)d_in[13];
    const float* n3g      = (const float*)d_in[14];
    const float* n3b      = (const float*)d_in[15];
    const float* off_w    = (const float*)d_in[16];
    const float* off_b    = (const float*)d_in[17];
    const float* aw_w     = (const float*)d_in[18];
    const float* aw_b     = (const float*)d_in[19];
    const float* val_w    = (const float*)d_in[20];
    const float* val_b    = (const float*)d_in[21];
    const float* ca_ow    = (const float*)d_in[22];
    const float* ca_ob    = (const float*)d_in[23];
    const float* l1w      = (const float*)d_in[24];
    const float* l1b      = (const float*)d_in[25];
    const float* l2w      = (const float*)d_in[26];
    const float* l2b      = (const float*)d_in[27];
    float* out = (float*)d_out;

    float *p_qin, *p_q, *p_k, *p_v, *p_sc, *p_ao, *p_t1, *p_tgt2, *p_qca,
          *p_off, *p_aw, *p_ca, *p_tgt3, *p_ffn, *p_value;
    cudaGetSymbolAddress((void**)&p_qin,  g_qin);
    cudaGetSymbolAddress((void**)&p_q,    g_q);
    cudaGetSymbolAddress((void**)&p_k,    g_k);
    cudaGetSymbolAddress((void**)&p_v,    g_v);
    cudaGetSymbolAddress((void**)&p_sc,   g_sc);
    cudaGetSymbolAddress((void**)&p_ao,   g_ao);
    cudaGetSymbolAddress((void**)&p_t1,   g_t1);
    cudaGetSymbolAddress((void**)&p_tgt2, g_tgt2);
    cudaGetSymbolAddress((void**)&p_qca,  g_qca);
    cudaGetSymbolAddress((void**)&p_off,  g_off);
    cudaGetSymbolAddress((void**)&p_aw,   g_aw);
    cudaGetSymbolAddress((void**)&p_ca,   g_ca);
    cudaGetSymbolAddress((void**)&p_tgt3, g_tgt3);
    cudaGetSymbolAddress((void**)&p_ffn,  g_ffn);
    cudaGetSymbolAddress((void**)&p_value, g_value);

    const int n = Tc*Dc;

    // q_in = tgt + pos
    add_k<<<n/256, 256>>>(tgt, pos, p_qin, n);

    // QKV projections -> [b,h,l,d] (tensor-core)
    launch_bgemm(p_qin, in_w,            in_b,       p_q, Tc, Dc, Dc, false, true);
    launch_bgemm(p_qin, in_w + 256*256,  in_b + 256, p_k, Tc, Dc, Dc, false, true);
    launch_bgemm(tgt,   in_w + 512*256,  in_b + 512, p_v, Tc, Dc, Dc, false, true);

    // scores: batched [bh] 900x900x32 (fp32)
    {
        dim3 grid((NQc + 127)/128, (NQc + 127)/128, BHc);
        sgemm128<<<grid, 256>>>(p_q, p_k, p_sc,
                                NQc, NQc, DHc,
                                NQc*DHc, NQc*DHc, (long long)NQc*NQc);
    }
    softmax_rows<<<BHc*NQc/8, 256>>>(p_sc);
    av_kernel<<<dim3((NQc + 127)/128, BHc), 256>>>(p_sc, p_v, p_ao);

    // out proj + residual + LN(norm2)
    launch_bgemm(p_ao, sa_ow, sa_ob, p_t1, Tc, Dc, Dc, false, false);
    residual_ln<<<Tc, 256>>>(tgt, p_t1, n2g, n2b, p_tgt2);

    // cross-attn query = tgt2 + pos
    add_k<<<n/256, 256>>>(p_tgt2, pos, p_qca, n);

    // value projection over memory (biggest GEMM, tensor-core)
    launch_bgemm(memory, val_w, val_b, p_value, Sc*Bc, Dc, Dc, false, false);

    // sampling offsets + attention weights
    launch_bgemm(p_qca, off_w, off_b, p_off, Tc, Dc, Dc, false, false);
    launch_bgemm(p_qca, aw_w,  aw_b,  p_aw,  Tc, 128, Dc, false, false);

    // MS-deformable sampling
    deform_kernel<<<dim3(NQc, Bc), 256>>>(p_off, p_aw, refpts, p_value, p_ca);

    // cross-attn out proj + residual + LN(norm1)
    launch_bgemm(p_ca, ca_ow, ca_ob, p_t1, Tc, Dc, Dc, false, false);
    residual_ln<<<Tc, 256>>>(p_tgt2, p_t1, n1g, n1b, p_tgt3);

    // FFN
    launch_bgemm(p_tgt3, l1w, l1b, p_ffn, Tc, DFFc, Dc, true,  false);
    launch_bgemm(p_ffn,  l2w, l2b, p_t1,  Tc, Dc, DFFc, false, false);
    residual_ln<<<Tc, 256>>>(p_tgt3, p_t1, n3g, n3b, out);
}

// round 11
// speedup vs baseline: 3.8064x; 1.3813x over previous
#include <cuda_runtime.h>
#include <cuda_bf16.h>
#include <cstdint>

#define NQc 900
#define Bc  8
#define Dc  256
#define Hc  8
#define DHc 32
#define NLc 4
#define NPc 4
#define DFFc 1024
#define Sc  19947
#define Tc  (NQc*Bc)        // 7200 tokens
#define BHc 64              // B*H batches

// ---------------- scratch (device globals; no allocation) ----------------
__device__ float g_qin [Tc*Dc];
__device__ float g_q   [BHc*NQc*DHc];   // [b*H+h][900][32]
__device__ float g_k   [BHc*NQc*DHc];
__device__ float g_v   [BHc*NQc*DHc];
__device__ float g_ao  [Tc*Dc];
__device__ float g_t1  [Tc*Dc];
__device__ float g_tgt2[Tc*Dc];
__device__ float g_qca [Tc*Dc];
__device__ float g_off [Tc*Dc];
__device__ float g_aw  [Tc*128];
__device__ float g_ca  [Tc*Dc];
__device__ float g_tgt3[Tc*Dc];
__device__ float g_ffn [Tc*DFFc];
__device__ float g_value[(size_t)Sc*Bc*Dc];

// ---------------- elementwise add ----------------
__global__ void add_k(const float* __restrict__ a, const float* __restrict__ b,
                      float* __restrict__ c, int n) {
    int i = blockIdx.x*256 + threadIdx.x;
    if (i < n) c[i] = a[i] + b[i];
}

// ---------------- MMA / split helpers ----------------
__device__ __forceinline__ void mma16816(float& d0, float& d1, float& d2, float& d3,
                                         uint32_t a0, uint32_t a1, uint32_t a2, uint32_t a3,
                                         uint32_t b0, uint32_t b1) {
    asm volatile(
        "mma.sync.aligned.m16n8k16.row.col.f32.bf16.bf16.f32 "
        "{%0,%1,%2,%3},{%4,%5,%6,%7},{%8,%9},{%0,%1,%2,%3};\n"
        : "+f"(d0), "+f"(d1), "+f"(d2), "+f"(d3)
        : "r"(a0), "r"(a1), "r"(a2), "r"(a3), "r"(b0), "r"(b1));
}

// split two floats into packed hi-bf16x2 (truncated) and lo-bf16x2 (rounded residual)
__device__ __forceinline__ void split2(float f0, float f1, uint32_t& hi, uint32_t& lo) {
    uint32_t u0 = __float_as_uint(f0) & 0xFFFF0000u;
    uint32_t u1 = __float_as_uint(f1) & 0xFFFF0000u;
    hi = (u0 >> 16) | u1;                  // low half = f0's bf16, high = f1's
    float r0 = f0 - __uint_as_float(u0);
    float r1 = f1 - __uint_as_float(u1);
    __nv_bfloat162 l = __floats2bfloat162_rn(r0, r1);
    lo = *reinterpret_cast<uint32_t*>(&l);
}

#define SWSTR 20   // words per row (16 used + 4 pad) -> conflict-free fragments

// ================= split-bf16 tensor-core GEMM =================
template<int RELU, int SCATTER>
__global__ __launch_bounds__(256)
void bgemm(const float* __restrict__ A, const float* __restrict__ W,
           const float* __restrict__ bias, float* __restrict__ C,
           int M, int N, int K) {
    __shared__ uint32_t sw[4][128][SWSTR];

    int tid = threadIdx.x;
    int warp = tid >> 5, lane = tid & 31;
    int g = lane >> 2, tg = lane & 3;
    int wm = warp >> 2, wn = warp & 3;
    int row0 = blockIdx.y * 128, col0 = blockIdx.x * 128;

    int lr = tid >> 1, half = tid & 1;
    bool aok = (row0 + lr) < M;
    const float* Aptr = A + (size_t)(row0 + lr) * K + half * 16;
    const float* Wptr = W + (size_t)(col0 + lr) * K + half * 16;

    float4 pa[4], pb[4];
    #pragma unroll
    for (int q = 0; q < 4; q++) {
        pa[q] = aok ? *(const float4*)(Aptr + q*4) : make_float4(0,0,0,0);
        pb[q] = *(const float4*)(Wptr + q*4);
    }

    float acc[4][4][4];
    #pragma unroll
    for (int i = 0; i < 4; i++)
        #pragma unroll
        for (int j = 0; j < 4; j++)
            #pragma unroll
            for (int e = 0; e < 4; e++) acc[i][j][e] = 0.f;

    int nStages = K >> 5;
    for (int s = 0; s < nStages; s++) {
        #pragma unroll
        for (int q = 0; q < 4; q++) {
            int c = half*8 + q*2;
            uint32_t h0, l0, h1, l1;
            split2(pa[q].x, pa[q].y, h0, l0);
            split2(pa[q].z, pa[q].w, h1, l1);
            sw[0][lr][c]   = h0; sw[0][lr][c+1] = h1;
            sw[1][lr][c]   = l0; sw[1][lr][c+1] = l1;
            split2(pb[q].x, pb[q].y, h0, l0);
            split2(pb[q].z, pb[q].w, h1, l1);
            sw[2][lr][c]   = h0; sw[2][lr][c+1] = h1;
            sw[3][lr][c]   = l0; sw[3][lr][c+1] = l1;
        }
        __syncthreads();

        if (s + 1 < nStages) {
            int k0 = (s + 1) << 5;
            #pragma unroll
            for (int q = 0; q < 4; q++) {
                pa[q] = aok ? *(const float4*)(Aptr + k0 + q*4) : make_float4(0,0,0,0);
                pb[q] = *(const float4*)(Wptr + k0 + q*4);
            }
        }

        #pragma unroll
        for (int ks = 0; ks < 2; ks++) {
            int cb = ks * 8;
            uint32_t bh[4][2], bl[4][2];
            #pragma unroll
            for (int j = 0; j < 4; j++) {
                int rB = wn*32 + j*8 + g;
                bh[j][0] = sw[2][rB][cb + tg];
                bh[j][1] = sw[2][rB][cb + tg + 4];
                bl[j][0] = sw[3][rB][cb + tg];
                bl[j][1] = sw[3][rB][cb + tg + 4];
            }
            #pragma unroll
            for (int i = 0; i < 4; i++) {
                int rA = wm*64 + i*16 + g;
                uint32_t ah0 = sw[0][rA][cb + tg];
                uint32_t ah1 = sw[0][rA+8][cb + tg];
                uint32_t ah2 = sw[0][rA][cb + tg + 4];
                uint32_t ah3 = sw[0][rA+8][cb + tg + 4];
                uint32_t al0 = sw[1][rA][cb + tg];
                uint32_t al1 = sw[1][rA+8][cb + tg];
                uint32_t al2 = sw[1][rA][cb + tg + 4];
                uint32_t al3 = sw[1][rA+8][cb + tg + 4];
                #pragma unroll
                for (int j = 0; j < 4; j++) {
                    float* d = acc[i][j];
                    mma16816(d[0],d[1],d[2],d[3], ah0,ah1,ah2,ah3, bh[j][0],bh[j][1]);
                    mma16816(d[0],d[1],d[2],d[3], ah0,ah1,ah2,ah3, bl[j][0],bl[j][1]);
                    mma16816(d[0],d[1],d[2],d[3], al0,al1,al2,al3, bh[j][0],bh[j][1]);
                }
            }
        }
        __syncthreads();
    }

    #pragma unroll
    for (int i = 0; i < 4; i++) {
        int r0 = row0 + wm*64 + i*16 + g;
        int r1 = r0 + 8;
        #pragma unroll
        for (int j = 0; j < 4; j++) {
            int c = col0 + wn*32 + j*8 + tg*2;
            float bx = bias ? bias[c] : 0.f;
            float by = bias ? bias[c+1] : 0.f;
            float v0 = acc[i][j][0] + bx, v1 = acc[i][j][1] + by;
            float v2 = acc[i][j][2] + bx, v3 = acc[i][j][3] + by;
            if (RELU) {
                v0 = fmaxf(v0, 0.f); v1 = fmaxf(v1, 0.f);
                v2 = fmaxf(v2, 0.f); v3 = fmaxf(v3, 0.f);
            }
            if (SCATTER) {
                int h = c >> 5, d = c & 31;
                if (r0 < M) {
                    int b = r0 & 7, l = r0 >> 3;
                    *(float2*)(C + (((size_t)(b*Hc + h))*NQc + l)*DHc + d) = make_float2(v0, v1);
                }
                if (r1 < M) {
                    int b = r1 & 7, l = r1 >> 3;
                    *(float2*)(C + (((size_t)(b*Hc + h))*NQc + l)*DHc + d) = make_float2(v2, v3);
                }
            } else {
                if (r0 < M) *(float2*)(C + (size_t)r0*N + c) = make_float2(v0, v1);
                if (r1 < M) *(float2*)(C + (size_t)r1*N + c) = make_float2(v2, v3);
            }
        }
    }
}

// ================= fused flash self-attention (split-bf16 MMA) =================
// grid (8 q-blocks, 64 bh), 256 threads. Q,K,V in [bh][900][32] fp32.
// Output O[l,b,256] fp32. Scale folded into Q.
__global__ __launch_bounds__(256)
void flash_attn(const float* __restrict__ Q, const float* __restrict__ K,
                const float* __restrict__ V, float* __restrict__ O) {
    __shared__ uint32_t sKh[128][SWSTR], sKl[128][SWSTR];
    __shared__ uint32_t sVh[32][68], sVl[32][68];

    int bh = blockIdx.y;
    int b = bh >> 3, h = bh & 7;
    int row0 = blockIdx.x * 128;
    int tid = threadIdx.x, warp = tid >> 5, lane = tid & 31;
    int g = lane >> 2, tg = lane & 3;

    const float* Qb = Q + (size_t)bh*NQc*DHc;
    const float* Kb = K + (size_t)bh*NQc*DHc;
    const float* Vb = V + (size_t)bh*NQc*DHc;

    // ---- Q fragments in registers (per warp: rows r0=.., r1=r0+8) ----
    int r0 = row0 + warp*16 + g, r1 = r0 + 8;
    uint32_t ah[2][4], al[2][4];
    {
        const float scale = 0.17677669529663689f;
        #pragma unroll
        for (int ch = 0; ch < 2; ch++) {
            #pragma unroll
            for (int e = 0; e < 4; e++) {
                int r = (e & 1) ? r1 : r0;
                int w = tg + ch*8 + (e>>1)*4;
                float2 v = make_float2(0.f, 0.f);
                if (r < NQc) v = *(const float2*)(Qb + (size_t)r*DHc + w*2);
                split2(v.x*scale, v.y*scale, ah[ch][e], al[ch][e]);
            }
        }
    }

    float s[16][4];
    float o[4][4];
    #pragma unroll
    for (int jd = 0; jd < 4; jd++)
        #pragma unroll
        for (int e = 0; e < 4; e++) o[jd][e] = 0.f;
    float m0 = -1e30f, m1 = -1e30f, l0 = 0.f, l1 = 0.f;

    for (int kt = 0; kt < 8; kt++) {
        int k0 = kt * 128;
        __syncthreads();
        // ---- stage K tile (split): each thread loads 16 floats (full half-row) ----
        {
            int r = tid >> 1, half = tid & 1;
            int kr = k0 + r;
            float4 f0 = make_float4(0,0,0,0), f1 = f0, f2 = f0, f3 = f0;
            if (kr < NQc) {
                const float* kp = Kb + (size_t)kr*DHc + half*16;
                f0 = *(const float4*)(kp);
                f1 = *(const float4*)(kp + 4);
                f2 = *(const float4*)(kp + 8);
                f3 = *(const float4*)(kp + 12);
            }
            uint32_t hh, ll;
            int wb = half*8;
            split2(f0.x, f0.y, hh, ll); sKh[r][wb+0] = hh; sKl[r][wb+0] = ll;
            split2(f0.z, f0.w, hh, ll); sKh[r][wb+1] = hh; sKl[r][wb+1] = ll;
            split2(f1.x, f1.y, hh, ll); sKh[r][wb+2] = hh; sKl[r][wb+2] = ll;
            split2(f1.z, f1.w, hh, ll); sKh[r][wb+3] = hh; sKl[r][wb+3] = ll;
            split2(f2.x, f2.y, hh, ll); sKh[r][wb+4] = hh; sKl[r][wb+4] = ll;
            split2(f2.z, f2.w, hh, ll); sKh[r][wb+5] = hh; sKl[r][wb+5] = ll;
            split2(f3.x, f3.y, hh, ll); sKh[r][wb+6] = hh; sKl[r][wb+6] = ll;
            split2(f3.z, f3.w, hh, ll); sKh[r][wb+7] = hh; sKl[r][wb+7] = ll;
        }
        // ---- stage V tile transposed (split): sV[d][keyword] ----
        {
            int r = tid & 63, dg = tid >> 6;       // key pair r, d group
            int ka = k0 + 2*r, kb = ka + 1;
            float4 a0 = make_float4(0,0,0,0), a1 = a0, c0 = a0, c1 = a0;
            if (ka < NQc) {
                a0 = *(const float4*)(Vb + (size_t)ka*DHc + dg*8);
                a1 = *(const float4*)(Vb + (size_t)ka*DHc + dg*8 + 4);
            }
            if (kb < NQc) {
                c0 = *(const float4*)(Vb + (size_t)kb*DHc + dg*8);
                c1 = *(const float4*)(Vb + (size_t)kb*DHc + dg*8 + 4);
            }
            float av[8] = {a0.x,a0.y,a0.z,a0.w,a1.x,a1.y,a1.z,a1.w};
            float cv[8] = {c0.x,c0.y,c0.z,c0.w,c1.x,c1.y,c1.z,c1.w};
            #pragma unroll
            for (int i = 0; i < 8; i++) {
                uint32_t hh, ll;
                split2(av[i], cv[i], hh, ll);
                sVh[dg*8 + i][r] = hh;
                sVl[dg*8 + i][r] = ll;
            }
        }
        __syncthreads();

        // ---- S = Q K^T (3-pass split) ----
        #pragma unroll
        for (int j = 0; j < 16; j++) {
            s[j][0] = s[j][1] = s[j][2] = s[j][3] = 0.f;
            int kr = j*8 + g;
            uint32_t b0 = sKh[kr][tg],   b1 = sKh[kr][tg+4];
            uint32_t b2 = sKh[kr][tg+8], b3 = sKh[kr][tg+12];
            uint32_t c0 = sKl[kr][tg],   c1 = sKl[kr][tg+4];
            uint32_t c2 = sKl[kr][tg+8], c3 = sKl[kr][tg+12];
            mma16816(s[j][0],s[j][1],s[j][2],s[j][3], ah[0][0],ah[0][1],ah[0][2],ah[0][3], b0,b1);
            mma16816(s[j][0],s[j][1],s[j][2],s[j][3], ah[1][0],ah[1][1],ah[1][2],ah[1][3], b2,b3);
            mma16816(s[j][0],s[j][1],s[j][2],s[j][3], ah[0][0],ah[0][1],ah[0][2],ah[0][3], c0,c1);
            mma16816(s[j][0],s[j][1],s[j][2],s[j][3], ah[1][0],ah[1][1],ah[1][2],ah[1][3], c2,c3);
            mma16816(s[j][0],s[j][1],s[j][2],s[j][3], al[0][0],al[0][1],al[0][2],al[0][3], b0,b1);
            mma16816(s[j][0],s[j][1],s[j][2],s[j][3], al[1][0],al[1][1],al[1][2],al[1][3], b2,b3);
        }

        // ---- mask tail cols >= 900 ----
        if (k0 + 128 > NQc) {
            #pragma unroll
            for (int j = 0; j < 16; j++) {
                int c0i = k0 + j*8 + 2*tg;
                if (c0i     >= NQc) { s[j][0] = -1e30f; s[j][2] = -1e30f; }
                if (c0i + 1 >= NQc) { s[j][1] = -1e30f; s[j][3] = -1e30f; }
            }
        }

        // ---- online softmax ----
        float mx0 = -1e30f, mx1 = -1e30f;
        #pragma unroll
        for (int j = 0; j < 16; j++) {
            mx0 = fmaxf(mx0, fmaxf(s[j][0], s[j][1]));
            mx1 = fmaxf(mx1, fmaxf(s[j][2], s[j][3]));
        }
        mx0 = fmaxf(mx0, __shfl_xor_sync(0xffffffffu, mx0, 1));
        mx0 = fmaxf(mx0, __shfl_xor_sync(0xffffffffu, mx0, 2));
        mx1 = fmaxf(mx1, __shfl_xor_sync(0xffffffffu, mx1, 1));
        mx1 = fmaxf(mx1, __shfl_xor_sync(0xffffffffu, mx1, 2));
        float mn0 = fmaxf(m0, mx0), mn1 = fmaxf(m1, mx1);
        float f0 = __expf(m0 - mn0), f1 = __expf(m1 - mn1);
        m0 = mn0; m1 = mn1;

        float sum0 = 0.f, sum1 = 0.f;
        #pragma unroll
        for (int j = 0; j < 16; j++) {
            s[j][0] = __expf(s[j][0] - m0);
            s[j][1] = __expf(s[j][1] - m0);
            s[j][2] = __expf(s[j][2] - m1);
            s[j][3] = __expf(s[j][3] - m1);
            sum0 += s[j][0] + s[j][1];
            sum1 += s[j][2] + s[j][3];
        }
        l0 = l0*f0 + sum0;
        l1 = l1*f1 + sum1;
        #pragma unroll
        for (int jd = 0; jd < 4; jd++) {
            o[jd][0] *= f0; o[jd][1] *= f0;
            o[jd][2] *= f1; o[jd][3] *= f1;
        }

        // ---- O += P V (3-pass split) ----
        #pragma unroll
        for (int c = 0; c < 8; c++) {
            uint32_t ph[4], pl[4];
            split2(s[2*c][0],   s[2*c][1],   ph[0], pl[0]);
            split2(s[2*c][2],   s[2*c][3],   ph[1], pl[1]);
            split2(s[2*c+1][0], s[2*c+1][1], ph[2], pl[2]);
            split2(s[2*c+1][2], s[2*c+1][3], ph[3], pl[3]);
            #pragma unroll
            for (int jd = 0; jd < 4; jd++) {
                int vr = jd*8 + g;
                uint32_t b0 = sVh[vr][c*8+tg], b1 = sVh[vr][c*8+tg+4];
                uint32_t d0 = sVl[vr][c*8+tg], d1 = sVl[vr][c*8+tg+4];
                mma16816(o[jd][0],o[jd][1],o[jd][2],o[jd][3], ph[0],ph[1],ph[2],ph[3], b0,b1);
                mma16816(o[jd][0],o[jd][1],o[jd][2],o[jd][3], ph[0],ph[1],ph[2],ph[3], d0,d1);
                mma16816(o[jd][0],o[jd][1],o[jd][2],o[jd][3], pl[0],pl[1],pl[2],pl[3], b0,b1);
            }
        }
    }

    // ---- normalize + store ----
    l0 += __shfl_xor_sync(0xffffffffu, l0, 1);
    l0 += __shfl_xor_sync(0xffffffffu, l0, 2);
    l1 += __shfl_xor_sync(0xffffffffu, l1, 1);
    l1 += __shfl_xor_sync(0xffffffffu, l1, 2);
    float inv0 = 1.f / l0, inv1 = 1.f / l1;
    if (r0 < NQc) {
        #pragma unroll
        for (int jd = 0; jd < 4; jd++)
            *(float2*)(O + ((size_t)r0*Bc + b)*Dc + h*DHc + jd*8 + tg*2)
                = make_float2(o[jd][0]*inv0, o[jd][1]*inv0);
    }
    if (r1 < NQc) {
        #pragma unroll
        for (int jd = 0; jd < 4; jd++)
            *(float2*)(O + ((size_t)r1*Bc + b)*Dc + h*DHc + jd*8 + tg*2)
                = make_float2(o[jd][2]*inv1, o[jd][3]*inv1);
    }
}

// ---------------- residual + LayerNorm ----------------
__global__ void residual_ln(const float* __restrict__ res, const float* __restrict__ x,
                            const float* __restrict__ g, const float* __restrict__ be,
                            float* __restrict__ out) {
    int t = blockIdx.x, i = threadIdx.x;
    float v = res[(size_t)t*Dc + i] + x[(size_t)t*Dc + i];
    __shared__ float red[8];
    __shared__ float mean_s, rstd_s;
    float s = v;
    #pragma unroll
    for (int o = 16; o; o >>= 1) s += __shfl_xor_sync(0xffffffffu, s, o);
    if ((i & 31) == 0) red[i >> 5] = s;
    __syncthreads();
    if (i < 32) {
        float t2 = (i < 8) ? red[i] : 0.f;
        #pragma unroll
        for (int o = 4; o; o >>= 1) t2 += __shfl_xor_sync(0xffffffffu, t2, o);
        if (i == 0) mean_s = t2 * (1.f/Dc);
    }
    __syncthreads();
    float m = mean_s;
    float d = v - m;
    float sq = d*d;
    #pragma unroll
    for (int o = 16; o; o >>= 1) sq += __shfl_xor_sync(0xffffffffu, sq, o);
    if ((i & 31) == 0) red[i >> 5] = sq;
    __syncthreads();
    if (i < 32) {
        float t2 = (i < 8) ? red[i] : 0.f;
        #pragma unroll
        for (int o = 4; o; o >>= 1) t2 += __shfl_xor_sync(0xffffffffu, t2, o);
        if (i == 0) rstd_s = rsqrtf(t2 * (1.f/Dc) + 1e-5f);
    }
    __syncthreads();
    out[(size_t)t*Dc + i] = d * rstd_s * g[i] + be[i];
}

// ---------------- MS-deformable attention sampling ----------------
__global__ void deform_kernel(const float* __restrict__ off, const float* __restrict__ aw,
                              const float* __restrict__ ref, const float* __restrict__ value,
                              float* __restrict__ out) {
    int q = blockIdx.x, b = blockIdx.y;
    int t = q*Bc + b;
    int tid = threadIdx.x, h = tid >> 5, lane = tid & 31;

    float a = (lane < 16) ? aw[(size_t)t*128 + h*16 + lane] : -1e30f;
    float mx = a;
    #pragma unroll
    for (int o = 16; o; o >>= 1) mx = fmaxf(mx, __shfl_xor_sync(0xffffffffu, mx, o));
    float e = (lane < 16) ? __expf(a - mx) : 0.f;
    float s = e;
    #pragma unroll
    for (int o = 16; o; o >>= 1) s += __shfl_xor_sync(0xffffffffu, s, o);
    float wgt = e / s;

    const float* rp = ref + (size_t)t*(NLc*4);
    const float* op = off + (size_t)t*Dc + h*32;
    const int HH[4] = {100,50,25,13};
    const int WW[4] = {150,75,38,19};
    const int ST[4] = {0,15000,18750,19700};
    float acc = 0.f;
    #pragma unroll
    for (int l = 0; l < NLc; l++) {
        float r0 = rp[l*4+0], r1 = rp[l*4+1], r2 = rp[l*4+2], r3 = rp[l*4+3];
        int Wd = WW[l], Hh = HH[l], st = ST[l];
        #pragma unroll
        for (int p = 0; p < NPc; p++) {
            int fo = (l*NPc + p)*2;
            float lx = r0 + op[fo]   * 0.125f * r2;
            float ly = r1 + op[fo+1] * 0.125f * r3;
            float x = lx * Wd - 0.5f;
            float y = ly * Hh - 0.5f;
            float wl = __shfl_sync(0xffffffffu, wgt, l*NPc + p);
            float x0f = floorf(x), y0f = floorf(y);
            int x0 = (int)x0f, y0 = (int)y0f;
            float fx = x - x0f, fy = y - y0f;
            float samp = 0.f;
            #pragma unroll
            for (int dy = 0; dy < 2; dy++) {
                #pragma unroll
                for (int dx = 0; dx < 2; dx++) {
                    int xi = x0 + dx, yi = y0 + dy;
                    if (xi >= 0 && xi < Wd && yi >= 0 && yi < Hh) {
                        float wc = (dx ? fx : 1.f-fx) * (dy ? fy : 1.f-fy);
                        samp += wc * value[((size_t)(st + yi*Wd + xi)*Bc + b)*Dc + h*DHc + lane];
                    }
                }
            }
            acc += wl * samp;
        }
    }
    out[(size_t)t*Dc + h*DHc + lane] = acc;
}

// ---------------- host helpers ----------------
static void launch_bgemm(const float* A, const float* W, const float* bias, float* C,
                         int M, int N, int K, bool relu, bool scatter) {
    dim3 grid(N/128, (M + 127)/128);
    if (scatter)      bgemm<0,1><<<grid, 256>>>(A, W, bias, C, M, N, K);
    else if (relu)    bgemm<1,0><<<grid, 256>>>(A, W, bias, C, M, N, K);
    else              bgemm<0,0><<<grid, 256>>>(A, W, bias, C, M, N, K);
}

extern "C" void kernel_launch(void* const* d_in, const int* in_sizes, int n_in,
                              void* d_out, int out_size) {
    const float* tgt      = (const float*)d_in[0];
    const float* pos      = (const float*)d_in[1];
    const float* refpts   = (const float*)d_in[2];
    const float* memory   = (const float*)d_in[3];
    const float* in_w     = (const float*)d_in[6];
    const float* in_b     = (const float*)d_in[7];
    const float* sa_ow    = (const float*)d_in[8];
    const float* sa_ob    = (const float*)d_in[9];
    const float* n1g      = (const float*)d_in[10];
    const float* n1b      = (const float*)d_in[11];
    const float* n2g      = (const float*)d_in[12];
    const float* n2b      = (const float*)d_in[13];
    const float* n3g      = (const float*)d_in[14];
    const float* n3b      = (const float*)d_in[15];
    const float* off_w    = (const float*)d_in[16];
    const float* off_b    = (const float*)d_in[17];
    const float* aw_w     = (const float*)d_in[18];
    const float* aw_b     = (const float*)d_in[19];
    const float* val_w    = (const float*)d_in[20];
    const float* val_b    = (const float*)d_in[21];
    const float* ca_ow    = (const float*)d_in[22];
    const float* ca_ob    = (const float*)d_in[23];
    const float* l1w      = (const float*)d_in[24];
    const float* l1b      = (const float*)d_in[25];
    const float* l2w      = (const float*)d_in[26];
    const float* l2b      = (const float*)d_in[27];
    float* out = (float*)d_out;

    float *p_qin, *p_q, *p_k, *p_v, *p_ao, *p_t1, *p_tgt2, *p_qca,
          *p_off, *p_aw, *p_ca, *p_tgt3, *p_ffn, *p_value;
    cudaGetSymbolAddress((void**)&p_qin,  g_qin);
    cudaGetSymbolAddress((void**)&p_q,    g_q);
    cudaGetSymbolAddress((void**)&p_k,    g_k);
    cudaGetSymbolAddress((void**)&p_v,    g_v);
    cudaGetSymbolAddress((void**)&p_ao,   g_ao);
    cudaGetSymbolAddress((void**)&p_t1,   g_t1);
    cudaGetSymbolAddress((void**)&p_tgt2, g_tgt2);
    cudaGetSymbolAddress((void**)&p_qca,  g_qca);
    cudaGetSymbolAddress((void**)&p_off,  g_off);
    cudaGetSymbolAddress((void**)&p_aw,   g_aw);
    cudaGetSymbolAddress((void**)&p_ca,   g_ca);
    cudaGetSymbolAddress((void**)&p_tgt3, g_tgt3);
    cudaGetSymbolAddress((void**)&p_ffn,  g_ffn);
    cudaGetSymbolAddress((void**)&p_value, g_value);

    const int n = Tc*Dc;

    // q_in = tgt + pos
    add_k<<<n/256, 256>>>(tgt, pos, p_qin, n);

    // QKV projections -> [b,h,l,d] (tensor-core)
    launch_bgemm(p_qin, in_w,            in_b,       p_q, Tc, Dc, Dc, false, true);
    launch_bgemm(p_qin, in_w + 256*256,  in_b + 256, p_k, Tc, Dc, Dc, false, true);
    launch_bgemm(tgt,   in_w + 512*256,  in_b + 512, p_v, Tc, Dc, Dc, false, true);

    // fused flash self-attention -> O[l,b,D]
    flash_attn<<<dim3(8, BHc), 256>>>(p_q, p_k, p_v, p_ao);

    // out proj + residual + LN(norm2)
    launch_bgemm(p_ao, sa_ow, sa_ob, p_t1, Tc, Dc, Dc, false, false);
    residual_ln<<<Tc, 256>>>(tgt, p_t1, n2g, n2b, p_tgt2);

    // cross-attn query = tgt2 + pos
    add_k<<<n/256, 256>>>(p_tgt2, pos, p_qca, n);

    // value projection over memory (biggest GEMM, tensor-core)
    launch_bgemm(memory, val_w, val_b, p_value, Sc*Bc, Dc, Dc, false, false);

    // sampling offsets + attention weights
    launch_bgemm(p_qca, off_w, off_b, p_off, Tc, Dc, Dc, false, false);
    launch_bgemm(p_qca, aw_w,  aw_b,  p_aw,  Tc, 128, Dc, false, false);

    // MS-deformable sampling
    deform_kernel<<<dim3(NQc, Bc), 256>>>(p_off, p_aw, refpts, p_value, p_ca);

    // cross-attn out proj + residual + LN(norm1)
    launch_bgemm(p_ca, ca_ow, ca_ob, p_t1, Tc, Dc, Dc, false, false);
    residual_ln<<<Tc, 256>>>(p_tgt2, p_t1, n1g, n1b, p_tgt3);

    // FFN
    launch_bgemm(p_tgt3, l1w, l1b, p_ffn, Tc, DFFc, Dc, true,  false);
    launch_bgemm(p_ffn,  l2w, l2b, p_t1,  Tc, Dc, DFFc, false, false);
    residual_ln<<<Tc, 256>>>(p_tgt3, p_t1, n3g, n3b, out);
}